// round 1
// baseline (speedup 1.0000x reference)
#include <cuda_runtime.h>

#define N_NODES 50000
#define N_EDGES 800000
// smem: w2 (64*512 floats) + transposed w1 (64*16 floats)
#define SW2_FLOATS 32768
#define SW1_FLOATS 1024
#define SMEM_BYTES ((SW2_FLOATS + SW1_FLOATS) * 4)

__device__ float g_esum[N_NODES * 8];

__global__ void zero_esum_kernel() {
    int i = blockIdx.x * blockDim.x + threadIdx.x;
    if (i < N_NODES * 8) g_esum[i] = 0.0f;
}

__global__ __launch_bounds__(512, 1)
void edge_kernel(const float* __restrict__ x,
                 const int*   __restrict__ ei,
                 const float* __restrict__ attr,
                 const float* __restrict__ emb,
                 const float* __restrict__ w1,
                 const float* __restrict__ w2,
                 float*       __restrict__ edge_out)
{
    extern __shared__ float smem[];
    float* sw2  = smem;               // [64][512]  col = a*128 + b*8 + k
    float* sw1t = smem + SW2_FLOATS;  // [64][16]   transposed: [c][d]

    {
        float4* d4 = (float4*)sw2;
        const float4* s4 = (const float4*)w2;
        for (int idx = threadIdx.x; idx < SW2_FLOATS / 4; idx += blockDim.x)
            d4[idx] = s4[idx];
        for (int idx = threadIdx.x; idx < SW1_FLOATS; idx += blockDim.x) {
            int c = idx >> 4, d = idx & 15;
            sw1t[idx] = w1[d * 64 + c];
        }
    }
    __syncthreads();

    const float4* sw2v = (const float4*)sw2;

    for (int e = blockIdx.x * blockDim.x + threadIdx.x; e < N_EDGES;
         e += gridDim.x * blockDim.x) {
        const int vi = ei[e];
        const int vj = ei[N_EDGES + e];

        // z = cat(x[i], x[j])
        float z[16];
        {
            const float4* xp = (const float4*)(x + (size_t)vi * 8);
            float4 t0 = xp[0], t1 = xp[1];
            z[0]=t0.x; z[1]=t0.y; z[2]=t0.z; z[3]=t0.w;
            z[4]=t1.x; z[5]=t1.y; z[6]=t1.z; z[7]=t1.w;
            const float4* xq = (const float4*)(x + (size_t)vj * 8);
            float4 u0 = xq[0], u1 = xq[1];
            z[8]=u0.x;  z[9]=u0.y;  z[10]=u0.z; z[11]=u0.w;
            z[12]=u1.x; z[13]=u1.y; z[14]=u1.z; z[15]=u1.w;
        }
        float at[4];
        {
            float4 a4 = ((const float4*)attr)[e];
            at[0]=a4.x; at[1]=a4.y; at[2]=a4.z; at[3]=a4.w;
        }
        float em[16];
        {
            const float4* ep = (const float4*)(emb + (size_t)e * 16);
            #pragma unroll
            for (int q = 0; q < 4; q++) {
                float4 t = ep[q];
                em[4*q+0]=t.x; em[4*q+1]=t.y; em[4*q+2]=t.z; em[4*q+3]=t.w;
            }
        }

        float acc[8];
        #pragma unroll
        for (int k = 0; k < 8; k++) acc[k] = 0.0f;

        #pragma unroll 1
        for (int c = 0; c < 64; c++) {
            // h[c] = silu((emb . w1[:,c]) / 4)   (computed on the fly)
            float s0 = 0.f, s1 = 0.f, s2 = 0.f, s3 = 0.f;
            const float4* w1c = (const float4*)(sw1t + c * 16);
            {
                float4 a0 = w1c[0], a1 = w1c[1], a2 = w1c[2], a3 = w1c[3];
                s0 = em[0]*a0.x + em[1]*a0.y + em[2]*a0.z + em[3]*a0.w;
                s1 = em[4]*a1.x + em[5]*a1.y + em[6]*a1.z + em[7]*a1.w;
                s2 = em[8]*a2.x + em[9]*a2.y + em[10]*a2.z + em[11]*a2.w;
                s3 = em[12]*a3.x + em[13]*a3.y + em[14]*a3.z + em[15]*a3.w;
            }
            float s = ((s0 + s1) + (s2 + s3)) * 0.25f;
            float hc = s / (1.0f + __expf(-s));   // silu

            const int base = c * 128;             // float4 index into sw2v
            #pragma unroll
            for (int a = 0; a < 4; a++) {
                float ha = hc * at[a];
                #pragma unroll
                for (int b = 0; b < 16; b++) {
                    float hab = ha * z[b];
                    float4 wA = sw2v[base + a * 32 + b * 2];
                    float4 wB = sw2v[base + a * 32 + b * 2 + 1];
                    acc[0] += hab * wA.x;
                    acc[1] += hab * wA.y;
                    acc[2] += hab * wA.z;
                    acc[3] += hab * wA.w;
                    acc[4] += hab * wB.x;
                    acc[5] += hab * wB.y;
                    acc[6] += hab * wB.z;
                    acc[7] += hab * wB.w;
                }
            }
        }

        // total path norm: (1/sqrt(64)) from h@w2, (1/sqrt(4*16)) from edge TP
        const float sc = 1.0f / 64.0f;
        float4 o0 = make_float4(acc[0]*sc, acc[1]*sc, acc[2]*sc, acc[3]*sc);
        float4 o1 = make_float4(acc[4]*sc, acc[5]*sc, acc[6]*sc, acc[7]*sc);
        float4* op = (float4*)(edge_out + (size_t)e * 8);
        op[0] = o0; op[1] = o1;

        float* es = g_esum + (size_t)vj * 8;
        atomicAdd(es + 0, o0.x); atomicAdd(es + 1, o0.y);
        atomicAdd(es + 2, o0.z); atomicAdd(es + 3, o0.w);
        atomicAdd(es + 4, o1.x); atomicAdd(es + 5, o1.y);
        atomicAdd(es + 6, o1.z); atomicAdd(es + 7, o1.w);
    }
}

__global__ __launch_bounds__(256)
void node_kernel(const float* __restrict__ x,
                 const float* __restrict__ w_node,
                 float*       __restrict__ x_out)
{
    __shared__ float swn[1024];   // [a][b][k] = a*128 + b*16 + k
    for (int idx = threadIdx.x; idx < 1024; idx += blockDim.x)
        swn[idx] = w_node[idx];
    __syncthreads();

    int n = blockIdx.x * blockDim.x + threadIdx.x;
    if (n >= N_NODES) return;

    float xv[8], ev[8];
    {
        const float4* xp = (const float4*)(x + (size_t)n * 8);
        float4 t0 = xp[0], t1 = xp[1];
        xv[0]=t0.x; xv[1]=t0.y; xv[2]=t0.z; xv[3]=t0.w;
        xv[4]=t1.x; xv[5]=t1.y; xv[6]=t1.z; xv[7]=t1.w;
        const float4* epp = (const float4*)(g_esum + (size_t)n * 8);
        float4 u0 = epp[0], u1 = epp[1];
        ev[0]=u0.x; ev[1]=u0.y; ev[2]=u0.z; ev[3]=u0.w;
        ev[4]=u1.x; ev[5]=u1.y; ev[6]=u1.z; ev[7]=u1.w;
    }

    float acc[16];
    #pragma unroll
    for (int k = 0; k < 16; k++) acc[k] = 0.0f;

    const float4* w4 = (const float4*)swn;
    #pragma unroll
    for (int a = 0; a < 8; a++) {
        #pragma unroll
        for (int b = 0; b < 8; b++) {
            float p = xv[a] * ev[b];
            int base = a * 32 + b * 4;  // float4 units
            float4 q0 = w4[base + 0], q1 = w4[base + 1];
            float4 q2 = w4[base + 2], q3 = w4[base + 3];
            acc[0]  += p * q0.x; acc[1]  += p * q0.y;
            acc[2]  += p * q0.z; acc[3]  += p * q0.w;
            acc[4]  += p * q1.x; acc[5]  += p * q1.y;
            acc[6]  += p * q1.z; acc[7]  += p * q1.w;
            acc[8]  += p * q2.x; acc[9]  += p * q2.y;
            acc[10] += p * q2.z; acc[11] += p * q2.w;
            acc[12] += p * q3.x; acc[13] += p * q3.y;
            acc[14] += p * q3.z; acc[15] += p * q3.w;
        }
    }

    const float sc = 0.125f;  // 1/sqrt(8*8)
    float4* op = (float4*)(x_out + (size_t)n * 16);
    op[0] = make_float4(acc[0]*sc,  acc[1]*sc,  acc[2]*sc,  acc[3]*sc);
    op[1] = make_float4(acc[4]*sc,  acc[5]*sc,  acc[6]*sc,  acc[7]*sc);
    op[2] = make_float4(acc[8]*sc,  acc[9]*sc,  acc[10]*sc, acc[11]*sc);
    op[3] = make_float4(acc[12]*sc, acc[13]*sc, acc[14]*sc, acc[15]*sc);
}

extern "C" void kernel_launch(void* const* d_in, const int* in_sizes, int n_in,
                              void* d_out, int out_size)
{
    const float* x    = (const float*)d_in[0];
    const int*   ei   = (const int*)  d_in[1];
    const float* attr = (const float*)d_in[2];
    const float* emb  = (const float*)d_in[3];
    const float* w1   = (const float*)d_in[4];
    const float* w2   = (const float*)d_in[5];
    const float* wn   = (const float*)d_in[6];

    float* out      = (float*)d_out;
    float* x_out    = out;                    // [N, 16]
    float* edge_out = out + N_NODES * 16;     // [E, 8]

    cudaFuncSetAttribute(edge_kernel,
                         cudaFuncAttributeMaxDynamicSharedMemorySize,
                         SMEM_BYTES);

    zero_esum_kernel<<<(N_NODES * 8 + 511) / 512, 512>>>();
    edge_kernel<<<304, 512, SMEM_BYTES>>>(x, ei, attr, emb, w1, w2, edge_out);
    node_kernel<<<(N_NODES + 255) / 256, 256>>>(x, wn, x_out);
}

// round 2
// speedup vs baseline: 1.0862x; 1.0862x over previous
#include <cuda_runtime.h>

#define N_NODES 50000
#define N_EDGES 800000
#define SW2_FLOATS 32768
#define SW1_FLOATS 1024
#define SMEM_BYTES ((SW2_FLOATS + SW1_FLOATS) * 4)

typedef unsigned long long u64;

__device__ float g_esum[N_NODES * 8];

__global__ void zero_esum_kernel() {
    int i = blockIdx.x * blockDim.x + threadIdx.x;
    if (i < N_NODES * 8) g_esum[i] = 0.0f;
}

__device__ __forceinline__ u64 pk(float lo, float hi) {
    u64 r;
    asm("mov.b64 %0, {%1, %2};" : "=l"(r) : "f"(lo), "f"(hi));
    return r;
}
__device__ __forceinline__ void unpk(u64 v, float& lo, float& hi) {
    asm("mov.b64 {%0, %1}, %2;" : "=f"(lo), "=f"(hi) : "l"(v));
}
__device__ __forceinline__ u64 mul2(u64 a, u64 b) {
    u64 r;
    asm("mul.rn.f32x2 %0, %1, %2;" : "=l"(r) : "l"(a), "l"(b));
    return r;
}
__device__ __forceinline__ void fma2(u64& d, u64 a, u64 b) {
    asm("fma.rn.f32x2 %0, %1, %2, %0;" : "+l"(d) : "l"(a), "l"(b));
}

__global__ __launch_bounds__(512, 1)
void edge_kernel(const float* __restrict__ x,
                 const int*   __restrict__ ei,
                 const float* __restrict__ attr,
                 const float* __restrict__ emb,
                 const float* __restrict__ w1,
                 const float* __restrict__ w2,
                 float*       __restrict__ edge_out)
{
    extern __shared__ float smem[];
    float* sw2  = smem;               // [64][512]  col = a*128 + b*8 + k
    float* sw1t = smem + SW2_FLOATS;  // [64][16]   transposed: [c][d]

    {
        float4* d4 = (float4*)sw2;
        const float4* s4 = (const float4*)w2;
        for (int idx = threadIdx.x; idx < SW2_FLOATS / 4; idx += blockDim.x)
            d4[idx] = s4[idx];
        for (int idx = threadIdx.x; idx < SW1_FLOATS; idx += blockDim.x) {
            int c = idx >> 4, d = idx & 15;
            sw1t[idx] = w1[d * 64 + c];
        }
    }
    __syncthreads();

    const ulonglong2* sw2q = (const ulonglong2*)sw2;  // 1 entry = 4 floats = 2 f32x2 pairs

    for (int e = blockIdx.x * blockDim.x + threadIdx.x; e < N_EDGES;
         e += gridDim.x * blockDim.x) {
        const int vi = ei[e];
        const int vj = ei[N_EDGES + e];

        // z = cat(x[i], x[j]) stored as duplicated (v,v) f32x2 pairs
        u64 zd[16];
        {
            const float4* xp = (const float4*)(x + (size_t)vi * 8);
            float4 t0 = xp[0], t1 = xp[1];
            zd[0]=pk(t0.x,t0.x); zd[1]=pk(t0.y,t0.y); zd[2]=pk(t0.z,t0.z); zd[3]=pk(t0.w,t0.w);
            zd[4]=pk(t1.x,t1.x); zd[5]=pk(t1.y,t1.y); zd[6]=pk(t1.z,t1.z); zd[7]=pk(t1.w,t1.w);
            const float4* xq = (const float4*)(x + (size_t)vj * 8);
            float4 u0 = xq[0], u1 = xq[1];
            zd[8]=pk(u0.x,u0.x);  zd[9]=pk(u0.y,u0.y);  zd[10]=pk(u0.z,u0.z); zd[11]=pk(u0.w,u0.w);
            zd[12]=pk(u1.x,u1.x); zd[13]=pk(u1.y,u1.y); zd[14]=pk(u1.z,u1.z); zd[15]=pk(u1.w,u1.w);
        }
        u64 atd[4];
        {
            float4 a4 = ((const float4*)attr)[e];
            atd[0]=pk(a4.x,a4.x); atd[1]=pk(a4.y,a4.y);
            atd[2]=pk(a4.z,a4.z); atd[3]=pk(a4.w,a4.w);
        }
        // emb as natural (d, d+1) pairs for the packed radial dot
        u64 em2[8];
        {
            const ulonglong2* ep = (const ulonglong2*)(emb + (size_t)e * 16);
            #pragma unroll
            for (int q = 0; q < 4; q++) {
                ulonglong2 t = ep[q];
                em2[2*q] = t.x; em2[2*q+1] = t.y;
            }
        }

        u64 acc[4];  // (k0,k1)(k2,k3)(k4,k5)(k6,k7)
        acc[0] = acc[1] = acc[2] = acc[3] = 0ULL;

        #pragma unroll 1
        for (int c = 0; c < 64; c++) {
            // h[c] = silu((emb . w1[:,c]) / 4) -- packed dot over 16 dims
            u64 sp = 0ULL;
            const ulonglong2* w1q = (const ulonglong2*)(sw1t + c * 16);
            #pragma unroll
            for (int q = 0; q < 4; q++) {
                ulonglong2 t = w1q[q];
                fma2(sp, em2[2*q],   t.x);
                fma2(sp, em2[2*q+1], t.y);
            }
            float slo, shi; unpk(sp, slo, shi);
            float s = (slo + shi) * 0.25f;
            float hc = s / (1.0f + __expf(-s));   // silu
            u64 hcd = pk(hc, hc);

            // float index of (c,a,b,k=0) = c*512 + a*128 + b*8 ; /4 -> ull2 idx
            #pragma unroll
            for (int a = 0; a < 4; a++) {
                u64 had = mul2(hcd, atd[a]);
                const int ab = c * 128 + a * 32;
                #pragma unroll
                for (int b = 0; b < 16; b++) {
                    u64 habp = mul2(had, zd[b]);        // (hab,hab)
                    ulonglong2 WA = sw2q[ab + b * 2];       // k0..k3
                    ulonglong2 WB = sw2q[ab + b * 2 + 1];   // k4..k7
                    fma2(acc[0], habp, WA.x);
                    fma2(acc[1], habp, WA.y);
                    fma2(acc[2], habp, WB.x);
                    fma2(acc[3], habp, WB.y);
                }
            }
        }

        // total path norm: (1/sqrt(64)) * (1/sqrt(4*16)) = 1/64
        const float sc = 1.0f / 64.0f;
        float o[8];
        unpk(acc[0], o[0], o[1]); unpk(acc[1], o[2], o[3]);
        unpk(acc[2], o[4], o[5]); unpk(acc[3], o[6], o[7]);
        #pragma unroll
        for (int k = 0; k < 8; k++) o[k] *= sc;

        float4* op = (float4*)(edge_out + (size_t)e * 8);
        op[0] = make_float4(o[0], o[1], o[2], o[3]);
        op[1] = make_float4(o[4], o[5], o[6], o[7]);

        float* es = g_esum + (size_t)vj * 8;
        #pragma unroll
        for (int k = 0; k < 8; k++) atomicAdd(es + k, o[k]);
    }
}

__global__ __launch_bounds__(256)
void node_kernel(const float* __restrict__ x,
                 const float* __restrict__ w_node,
                 float*       __restrict__ x_out)
{
    __shared__ float swn[1024];   // [a][b][k] = a*128 + b*16 + k
    for (int idx = threadIdx.x; idx < 1024; idx += blockDim.x)
        swn[idx] = w_node[idx];
    __syncthreads();

    int n = blockIdx.x * blockDim.x + threadIdx.x;
    if (n >= N_NODES) return;

    float xv[8], ev[8];
    {
        const float4* xp = (const float4*)(x + (size_t)n * 8);
        float4 t0 = xp[0], t1 = xp[1];
        xv[0]=t0.x; xv[1]=t0.y; xv[2]=t0.z; xv[3]=t0.w;
        xv[4]=t1.x; xv[5]=t1.y; xv[6]=t1.z; xv[7]=t1.w;
        const float4* epp = (const float4*)(g_esum + (size_t)n * 8);
        float4 u0 = epp[0], u1 = epp[1];
        ev[0]=u0.x; ev[1]=u0.y; ev[2]=u0.z; ev[3]=u0.w;
        ev[4]=u1.x; ev[5]=u1.y; ev[6]=u1.z; ev[7]=u1.w;
    }

    u64 acc[8];
    #pragma unroll
    for (int q = 0; q < 8; q++) acc[q] = 0ULL;

    const ulonglong2* w4 = (const ulonglong2*)swn;
    #pragma unroll
    for (int a = 0; a < 8; a++) {
        #pragma unroll
        for (int b = 0; b < 8; b++) {
            float p = xv[a] * ev[b];
            u64 pd = pk(p, p);
            int base = (a * 128 + b * 16) / 4;   // ulonglong2 units
            #pragma unroll
            for (int q = 0; q < 4; q++) {
                ulonglong2 w = w4[base + q];
                fma2(acc[2*q],   pd, w.x);
                fma2(acc[2*q+1], pd, w.y);
            }
        }
    }

    const float sc = 0.125f;  // 1/sqrt(8*8)
    float o[16];
    #pragma unroll
    for (int q = 0; q < 8; q++) { unpk(acc[q], o[2*q], o[2*q+1]); }
    float4* op = (float4*)(x_out + (size_t)n * 16);
    op[0] = make_float4(o[0]*sc,  o[1]*sc,  o[2]*sc,  o[3]*sc);
    op[1] = make_float4(o[4]*sc,  o[5]*sc,  o[6]*sc,  o[7]*sc);
    op[2] = make_float4(o[8]*sc,  o[9]*sc,  o[10]*sc, o[11]*sc);
    op[3] = make_float4(o[12]*sc, o[13]*sc, o[14]*sc, o[15]*sc);
}

extern "C" void kernel_launch(void* const* d_in, const int* in_sizes, int n_in,
                              void* d_out, int out_size)
{
    const float* x    = (const float*)d_in[0];
    const int*   ei   = (const int*)  d_in[1];
    const float* attr = (const float*)d_in[2];
    const float* emb  = (const float*)d_in[3];
    const float* w1   = (const float*)d_in[4];
    const float* w2   = (const float*)d_in[5];
    const float* wn   = (const float*)d_in[6];

    float* out      = (float*)d_out;
    float* x_out    = out;                    // [N, 16]
    float* edge_out = out + N_NODES * 16;     // [E, 8]

    cudaFuncSetAttribute(edge_kernel,
                         cudaFuncAttributeMaxDynamicSharedMemorySize,
                         SMEM_BYTES);

    zero_esum_kernel<<<(N_NODES * 8 + 511) / 512, 512>>>();
    edge_kernel<<<148, 512, SMEM_BYTES>>>(x, ei, attr, emb, w1, w2, edge_out);
    node_kernel<<<(N_NODES + 255) / 256, 256>>>(x, wn, x_out);
}

// round 4
// speedup vs baseline: 2.0684x; 1.9042x over previous
#include <cuda_runtime.h>
#include <cuda_bf16.h>
#include <cstdint>

#define N_NODES 50000
#define N_EDGES 800000
#define TILE_M  256
#define NTILES  (N_EDGES / TILE_M)   // 3125

#define HSTRIDE 136                   // h row pitch in bytes (64 bf16 = 128B + 8 pad)

// ---- smem layout (bytes) ----
#define OFF_BP   0                                  // B fragments packed: 64nt*4ks*32lane*16B
#define OFF_HHI  131072                             // 256 rows * HSTRIDE
#define OFF_HLO  (OFF_HHI + 256*HSTRIDE)
#define OFF_Z    (OFF_HLO + 256*HSTRIDE)            // 256 * 16 f32
#define OFF_AT   (OFF_Z  + 256*64)                  // 256 * 4 f32
#define OFF_VJ   (OFF_AT + 256*16)                  // 256 int
#define OFF_W1T  (OFF_VJ + 256*4)                   // 64*16 f32 transposed
#define SMEM_TOTAL (OFF_W1T + 4096)                 // 226304 B

__device__ float g_esum[N_NODES * 8];

__global__ void zero_esum_kernel() {
    int i = blockIdx.x * blockDim.x + threadIdx.x;
    if (i < N_NODES * 8) g_esum[i] = 0.0f;
}

// pack two f32 -> bf16x2 (lo -> low half, hi -> high half)
__device__ __forceinline__ uint32_t pack_bf16x2(float lo, float hi) {
    uint32_t r;
    asm("cvt.rn.bf16x2.f32 %0, %1, %2;" : "=r"(r) : "f"(hi), "f"(lo));
    return r;
}

__device__ __forceinline__ void mma_bf16(float d[4],
                                         uint32_t a0, uint32_t a1, uint32_t a2, uint32_t a3,
                                         uint32_t b0, uint32_t b1) {
    asm volatile(
        "mma.sync.aligned.m16n8k16.row.col.f32.bf16.bf16.f32 "
        "{%0,%1,%2,%3}, {%4,%5,%6,%7}, {%8,%9}, {%0,%1,%2,%3};"
        : "+f"(d[0]), "+f"(d[1]), "+f"(d[2]), "+f"(d[3])
        : "r"(a0), "r"(a1), "r"(a2), "r"(a3), "r"(b0), "r"(b1));
}

__global__ __launch_bounds__(128, 1)
void edge_kernel(const float* __restrict__ x,
                 const int*   __restrict__ ei,
                 const float* __restrict__ attr,
                 const float* __restrict__ emb,
                 const float* __restrict__ w1,
                 const float* __restrict__ w2,
                 float*       __restrict__ edge_out)
{
    extern __shared__ char smem[];
    const int tid  = threadIdx.x;
    const int lane = tid & 31;
    const int gID  = lane >> 2;
    const int tig  = lane & 3;
    const int wid  = tid >> 5;

    float* sw1t = (float*)(smem + OFF_W1T);
    // ---- preload w1 transposed [c][d] ----
    for (int idx = tid; idx < 1024; idx += blockDim.x) {
        int c = idx >> 4, d = idx & 15;
        sw1t[idx] = w1[d * 64 + c];
    }
    // ---- preload W2 as packed B fragments (hi/lo bf16 split) ----
    // entry (nt, ks, lane): n = nt*8 + lane/4 ; k0 = ks*16 + (lane%4)*2
    // 16B = { hi(k0),hi(k0+1) | hi(k0+8),hi(k0+9) | lo(k0),lo(k0+1) | lo(k0+8),lo(k0+9) }
    for (int ent = tid; ent < 8192; ent += blockDim.x) {
        int l  = ent & 31;
        int ks = (ent >> 5) & 3;
        int nt = ent >> 7;
        int n  = nt * 8 + (l >> 2);
        int k0 = ks * 16 + (l & 3) * 2;
        float v0 = w2[(k0    ) * 512 + n];
        float v1 = w2[(k0 + 1) * 512 + n];
        float v2 = w2[(k0 + 8) * 512 + n];
        float v3 = w2[(k0 + 9) * 512 + n];
        float h0 = __bfloat162float(__float2bfloat16_rn(v0));
        float h1 = __bfloat162float(__float2bfloat16_rn(v1));
        float h2 = __bfloat162float(__float2bfloat16_rn(v2));
        float h3 = __bfloat162float(__float2bfloat16_rn(v3));
        uint4 pk;
        pk.x = pack_bf16x2(h0, h1);
        pk.y = pack_bf16x2(h2, h3);
        pk.z = pack_bf16x2(v0 - h0, v1 - h1);
        pk.w = pack_bf16x2(v2 - h2, v3 - h3);
        *(uint4*)(smem + OFF_BP + (size_t)ent * 16) = pk;
    }
    __syncthreads();

    for (int tile = blockIdx.x; tile < NTILES; tile += gridDim.x) {
        // ================= phase 1: per-edge h + staging =================
        #pragma unroll
        for (int s = 0; s < 2; s++) {
            const int row = tid + s * 128;
            const int e   = tile * TILE_M + row;

            float em[16];
            {
                const float4* ep = (const float4*)(emb + (size_t)e * 16);
                #pragma unroll
                for (int q = 0; q < 4; q++) {
                    float4 t = ep[q];
                    em[4*q]=t.x; em[4*q+1]=t.y; em[4*q+2]=t.z; em[4*q+3]=t.w;
                }
            }
            char* hhi = smem + OFF_HHI + row * HSTRIDE;
            char* hlo = smem + OFF_HLO + row * HSTRIDE;
            #pragma unroll 4
            for (int c = 0; c < 64; c += 2) {
                float sa = 0.f, sb = 0.f;
                const float* wa = sw1t + c * 16;
                const float* wb = wa + 16;
                #pragma unroll
                for (int d = 0; d < 16; d++) {
                    sa += em[d] * wa[d];
                    sb += em[d] * wb[d];
                }
                sa *= 0.25f; sb *= 0.25f;
                float ha = sa / (1.0f + __expf(-sa));
                float hb = sb / (1.0f + __expf(-sb));
                float ha_h = __bfloat162float(__float2bfloat16_rn(ha));
                float hb_h = __bfloat162float(__float2bfloat16_rn(hb));
                *(uint32_t*)(hhi + c * 2) = pack_bf16x2(ha_h, hb_h);
                *(uint32_t*)(hlo + c * 2) = pack_bf16x2(ha - ha_h, hb - hb_h);
            }

            const int vi = ei[e];
            const int vj = ei[N_EDGES + e];
            float4* zr = (float4*)(smem + OFF_Z + row * 64);
            const float4* xp = (const float4*)(x + (size_t)vi * 8);
            zr[0] = xp[0]; zr[1] = xp[1];
            const float4* xq = (const float4*)(x + (size_t)vj * 8);
            zr[2] = xq[0]; zr[3] = xq[1];
            *(float4*)(smem + OFF_AT + row * 16) = ((const float4*)attr)[e];
            *(int*)(smem + OFF_VJ + row * 4) = vj;
        }
        __syncthreads();

        // ================= phase 2: MMA + fused epilogue =================
        const int wbase = wid * 64;
        #pragma unroll 1
        for (int mt = 0; mt < 4; mt++) {
            const int r0 = wbase + mt * 16 + gID;
            const int r8 = r0 + 8;

            // A fragments (h hi/lo), all 4 k-steps
            uint32_t ahi[4][4], alo[4][4];
            {
                const char* p0h = smem + OFF_HHI + r0 * HSTRIDE + tig * 4;
                const char* p8h = smem + OFF_HHI + r8 * HSTRIDE + tig * 4;
                const char* p0l = smem + OFF_HLO + r0 * HSTRIDE + tig * 4;
                const char* p8l = smem + OFF_HLO + r8 * HSTRIDE + tig * 4;
                #pragma unroll
                for (int ks = 0; ks < 4; ks++) {
                    ahi[ks][0] = *(const uint32_t*)(p0h + ks * 32);
                    ahi[ks][1] = *(const uint32_t*)(p8h + ks * 32);
                    ahi[ks][2] = *(const uint32_t*)(p0h + ks * 32 + 16);
                    ahi[ks][3] = *(const uint32_t*)(p8h + ks * 32 + 16);
                    alo[ks][0] = *(const uint32_t*)(p0l + ks * 32);
                    alo[ks][1] = *(const uint32_t*)(p8l + ks * 32);
                    alo[ks][2] = *(const uint32_t*)(p0l + ks * 32 + 16);
                    alo[ks][3] = *(const uint32_t*)(p8l + ks * 32 + 16);
                }
            }
            // per-row z / attr in registers
            float z0[16], z1[16], at0[4], at1[4];
            {
                const float4* q0 = (const float4*)(smem + OFF_Z + r0 * 64);
                const float4* q1 = (const float4*)(smem + OFF_Z + r8 * 64);
                #pragma unroll
                for (int q = 0; q < 4; q++) {
                    float4 a = q0[q]; z0[4*q]=a.x; z0[4*q+1]=a.y; z0[4*q+2]=a.z; z0[4*q+3]=a.w;
                    float4 b = q1[q]; z1[4*q]=b.x; z1[4*q+1]=b.y; z1[4*q+2]=b.z; z1[4*q+3]=b.w;
                }
                float4 a = *(const float4*)(smem + OFF_AT + r0 * 16);
                at0[0]=a.x; at0[1]=a.y; at0[2]=a.z; at0[3]=a.w;
                float4 b = *(const float4*)(smem + OFF_AT + r8 * 16);
                at1[0]=b.x; at1[1]=b.y; at1[2]=b.z; at1[3]=b.w;
            }

            float acc0 = 0.f, acc1 = 0.f, acc2 = 0.f, acc3 = 0.f;

            #pragma unroll 4
            for (int nt = 0; nt < 64; nt++) {
                float dhh[4] = {0,0,0,0}, dhl[4] = {0,0,0,0}, dlh[4] = {0,0,0,0};
                const uint4* bp = (const uint4*)(smem + OFF_BP + (size_t)nt * 2048) + lane;
                #pragma unroll
                for (int ks = 0; ks < 4; ks++) {
                    uint4 b = bp[ks * 32];
                    mma_bf16(dhh, ahi[ks][0], ahi[ks][1], ahi[ks][2], ahi[ks][3], b.x, b.y);
                    mma_bf16(dhl, ahi[ks][0], ahi[ks][1], ahi[ks][2], ahi[ks][3], b.z, b.w);
                    mma_bf16(dlh, alo[ks][0], alo[ks][1], alo[ks][2], alo[ks][3], b.x, b.y);
                }
                const int a = nt >> 4, b = nt & 15;
                const float c0 = at0[a] * z0[b];
                const float c1 = at1[a] * z1[b];
                acc0 += c0 * (dhh[0] + dhl[0] + dlh[0]);
                acc1 += c0 * (dhh[1] + dhl[1] + dlh[1]);
                acc2 += c1 * (dhh[2] + dhl[2] + dlh[2]);
                acc3 += c1 * (dhh[3] + dhl[3] + dlh[3]);
            }

            const float sc = 1.0f / 64.0f;
            acc0 *= sc; acc1 *= sc; acc2 *= sc; acc3 *= sc;
            const int e0 = tile * TILE_M + r0;
            const int e1 = tile * TILE_M + r8;
            *(float2*)(edge_out + (size_t)e0 * 8 + 2 * tig) = make_float2(acc0, acc1);
            *(float2*)(edge_out + (size_t)e1 * 8 + 2 * tig) = make_float2(acc2, acc3);
            const int vj0 = *(const int*)(smem + OFF_VJ + r0 * 4);
            const int vj1 = *(const int*)(smem + OFF_VJ + r8 * 4);
            atomicAdd(g_esum + (size_t)vj0 * 8 + 2 * tig,     acc0);
            atomicAdd(g_esum + (size_t)vj0 * 8 + 2 * tig + 1, acc1);
            atomicAdd(g_esum + (size_t)vj1 * 8 + 2 * tig,     acc2);
            atomicAdd(g_esum + (size_t)vj1 * 8 + 2 * tig + 1, acc3);
        }
        __syncthreads();   // protect h_s / z_s reuse next tile
    }
}

__global__ __launch_bounds__(256)
void node_kernel(const float* __restrict__ x,
                 const float* __restrict__ w_node,
                 float*       __restrict__ x_out)
{
    __shared__ float swn[1024];   // [a][b][k]
    for (int idx = threadIdx.x; idx < 1024; idx += blockDim.x)
        swn[idx] = w_node[idx];
    __syncthreads();

    int n = blockIdx.x * blockDim.x + threadIdx.x;
    if (n >= N_NODES) return;

    float xv[8], ev[8];
    {
        const float4* xp = (const float4*)(x + (size_t)n * 8);
        float4 t0 = xp[0], t1 = xp[1];
        xv[0]=t0.x; xv[1]=t0.y; xv[2]=t0.z; xv[3]=t0.w;
        xv[4]=t1.x; xv[5]=t1.y; xv[6]=t1.z; xv[7]=t1.w;
        const float4* epp = (const float4*)(g_esum + (size_t)n * 8);
        float4 u0 = epp[0], u1 = epp[1];
        ev[0]=u0.x; ev[1]=u0.y; ev[2]=u0.z; ev[3]=u0.w;
        ev[4]=u1.x; ev[5]=u1.y; ev[6]=u1.z; ev[7]=u1.w;
    }

    float acc[16];
    #pragma unroll
    for (int k = 0; k < 16; k++) acc[k] = 0.0f;

    const float4* w4 = (const float4*)swn;
    #pragma unroll
    for (int a = 0; a < 8; a++) {
        #pragma unroll
        for (int b = 0; b < 8; b++) {
            float p = xv[a] * ev[b];
            int base = a * 32 + b * 4;
            float4 q0 = w4[base], q1 = w4[base+1], q2 = w4[base+2], q3 = w4[base+3];
            acc[0]+=p*q0.x;  acc[1]+=p*q0.y;  acc[2]+=p*q0.z;  acc[3]+=p*q0.w;
            acc[4]+=p*q1.x;  acc[5]+=p*q1.y;  acc[6]+=p*q1.z;  acc[7]+=p*q1.w;
            acc[8]+=p*q2.x;  acc[9]+=p*q2.y;  acc[10]+=p*q2.z; acc[11]+=p*q2.w;
            acc[12]+=p*q3.x; acc[13]+=p*q3.y; acc[14]+=p*q3.z; acc[15]+=p*q3.w;
        }
    }

    const float sc = 0.125f;
    float4* op = (float4*)(x_out + (size_t)n * 16);
    op[0] = make_float4(acc[0]*sc,  acc[1]*sc,  acc[2]*sc,  acc[3]*sc);
    op[1] = make_float4(acc[4]*sc,  acc[5]*sc,  acc[6]*sc,  acc[7]*sc);
    op[2] = make_float4(acc[8]*sc,  acc[9]*sc,  acc[10]*sc, acc[11]*sc);
    op[3] = make_float4(acc[12]*sc, acc[13]*sc, acc[14]*sc, acc[15]*sc);
}

extern "C" void kernel_launch(void* const* d_in, const int* in_sizes, int n_in,
                              void* d_out, int out_size)
{
    const float* x    = (const float*)d_in[0];
    const int*   ei   = (const int*)  d_in[1];
    const float* attr = (const float*)d_in[2];
    const float* emb  = (const float*)d_in[3];
    const float* w1   = (const float*)d_in[4];
    const float* w2   = (const float*)d_in[5];
    const float* wn   = (const float*)d_in[6];

    float* out      = (float*)d_out;
    float* x_out    = out;                    // [N, 16]
    float* edge_out = out + N_NODES * 16;     // [E, 8]

    static int attr_set = 0;
    if (!attr_set) {
        cudaFuncSetAttribute(edge_kernel,
                             cudaFuncAttributeMaxDynamicSharedMemorySize,
                             SMEM_TOTAL);
        attr_set = 1;
    }

    zero_esum_kernel<<<(N_NODES * 8 + 511) / 512, 512>>>();
    edge_kernel<<<148, 128, SMEM_TOTAL>>>(x, ei, attr, emb, w1, w2, edge_out);
    node_kernel<<<(N_NODES + 255) / 256, 256>>>(x, wn, x_out);
}

// round 5
// speedup vs baseline: 2.5169x; 1.2168x over previous
#include <cuda_runtime.h>
#include <cuda_fp16.h>
#include <cstdint>

#define N_NODES 50000
#define N_EDGES 800000
#define TILE_M  256
#define NTILES  (N_EDGES / TILE_M)   // 3125

#define HSTRIDE 136                   // h row pitch in bytes (64 fp16 = 128B + 8 pad)

// ---- smem layout (bytes) ----
#define OFF_BP   0                                  // B fragments: 64nt*4ks*32lane*16B = 128K
#define OFF_H    131072                             // 256 rows * HSTRIDE (h in fp16)
#define OFF_Z    (OFF_H  + 256*HSTRIDE)             // 256 * 16 f32
#define OFF_AT   (OFF_Z  + 256*64)                  // 256 * 4 f32
#define OFF_VJ   (OFF_AT + 256*16)                  // 256 int
#define OFF_W1T  (OFF_VJ + 256*4)                   // 64*16 f32 transposed
#define SMEM_TOTAL (OFF_W1T + 4096)                 // ~191.5 KB

__device__ float g_esum[N_NODES * 8];

__global__ void zero_esum_kernel() {
    int i = blockIdx.x * blockDim.x + threadIdx.x;
    if (i < N_NODES * 8) g_esum[i] = 0.0f;
}

// pack two f32 -> f16x2 (first arg -> low half)
__device__ __forceinline__ uint32_t pack_f16x2(float lo, float hi) {
    uint32_t r;
    asm("cvt.rn.f16x2.f32 %0, %1, %2;" : "=r"(r) : "f"(hi), "f"(lo));
    return r;
}

__device__ __forceinline__ void mma_f16(float d[4],
                                        uint32_t a0, uint32_t a1, uint32_t a2, uint32_t a3,
                                        uint32_t b0, uint32_t b1) {
    asm volatile(
        "mma.sync.aligned.m16n8k16.row.col.f32.f16.f16.f32 "
        "{%0,%1,%2,%3}, {%4,%5,%6,%7}, {%8,%9}, {%0,%1,%2,%3};"
        : "+f"(d[0]), "+f"(d[1]), "+f"(d[2]), "+f"(d[3])
        : "r"(a0), "r"(a1), "r"(a2), "r"(a3), "r"(b0), "r"(b1));
}

// first k-step: C = 0 (no accumulator zero-MOVs)
__device__ __forceinline__ void mma_f16_z(float d[4],
                                          uint32_t a0, uint32_t a1, uint32_t a2, uint32_t a3,
                                          uint32_t b0, uint32_t b1, float zz) {
    asm volatile(
        "mma.sync.aligned.m16n8k16.row.col.f32.f16.f16.f32 "
        "{%0,%1,%2,%3}, {%4,%5,%6,%7}, {%8,%9}, {%10,%10,%10,%10};"
        : "=f"(d[0]), "=f"(d[1]), "=f"(d[2]), "=f"(d[3])
        : "r"(a0), "r"(a1), "r"(a2), "r"(a3), "r"(b0), "r"(b1), "f"(zz));
}

__global__ __launch_bounds__(128, 1)
void edge_kernel(const float* __restrict__ x,
                 const int*   __restrict__ ei,
                 const float* __restrict__ attr,
                 const float* __restrict__ emb,
                 const float* __restrict__ w1,
                 const float* __restrict__ w2,
                 float*       __restrict__ edge_out)
{
    extern __shared__ char smem[];
    const int tid  = threadIdx.x;
    const int lane = tid & 31;
    const int gID  = lane >> 2;
    const int tig  = lane & 3;
    const int wid  = tid >> 5;

    float* sw1t = (float*)(smem + OFF_W1T);
    for (int idx = tid; idx < 1024; idx += blockDim.x) {
        int c = idx >> 4, d = idx & 15;
        sw1t[idx] = w1[d * 64 + c];
    }
    // ---- preload W2 as packed B fragments (fp16 hi/lo split of W2) ----
    // entry (nt, ks, lane): n = nt*8 + lane/4 ; k0 = ks*16 + (lane%4)*2
    // 16B = { hi(k0),hi(k0+1) | hi(k0+8),hi(k0+9) | lo(k0),lo(k0+1) | lo(k0+8),lo(k0+9) }
    for (int ent = tid; ent < 8192; ent += blockDim.x) {
        int l  = ent & 31;
        int ks = (ent >> 5) & 3;
        int nt = ent >> 7;
        int n  = nt * 8 + (l >> 2);
        int k0 = ks * 16 + (l & 3) * 2;
        float v0 = w2[(k0    ) * 512 + n];
        float v1 = w2[(k0 + 1) * 512 + n];
        float v2 = w2[(k0 + 8) * 512 + n];
        float v3 = w2[(k0 + 9) * 512 + n];
        float h0 = __half2float(__float2half_rn(v0));
        float h1 = __half2float(__float2half_rn(v1));
        float h2 = __half2float(__float2half_rn(v2));
        float h3 = __half2float(__float2half_rn(v3));
        uint4 pk;
        pk.x = pack_f16x2(h0, h1);
        pk.y = pack_f16x2(h2, h3);
        pk.z = pack_f16x2(v0 - h0, v1 - h1);
        pk.w = pack_f16x2(v2 - h2, v3 - h3);
        *(uint4*)(smem + OFF_BP + (size_t)ent * 16) = pk;
    }
    __syncthreads();

    for (int tile = blockIdx.x; tile < NTILES; tile += gridDim.x) {
        // ================= phase 1: per-edge h + staging =================
        #pragma unroll
        for (int s = 0; s < 2; s++) {
            const int row = tid + s * 128;
            const int e   = tile * TILE_M + row;

            float em[16];
            {
                const float4* ep = (const float4*)(emb + (size_t)e * 16);
                #pragma unroll
                for (int q = 0; q < 4; q++) {
                    float4 t = ep[q];
                    em[4*q]=t.x; em[4*q+1]=t.y; em[4*q+2]=t.z; em[4*q+3]=t.w;
                }
            }
            char* hrow = smem + OFF_H + row * HSTRIDE;
            #pragma unroll 4
            for (int c = 0; c < 64; c += 2) {
                float sa = 0.f, sb = 0.f;
                const float* wa = sw1t + c * 16;
                const float* wb = wa + 16;
                #pragma unroll
                for (int d = 0; d < 16; d++) {
                    sa += em[d] * wa[d];
                    sb += em[d] * wb[d];
                }
                sa *= 0.25f; sb *= 0.25f;
                float ha = sa / (1.0f + __expf(-sa));
                float hb = sb / (1.0f + __expf(-sb));
                *(uint32_t*)(hrow + c * 2) = pack_f16x2(ha, hb);
            }

            const int vi = ei[e];
            const int vj = ei[N_EDGES + e];
            float4* zr = (float4*)(smem + OFF_Z + row * 64);
            const float4* xp = (const float4*)(x + (size_t)vi * 8);
            zr[0] = xp[0]; zr[1] = xp[1];
            const float4* xq = (const float4*)(x + (size_t)vj * 8);
            zr[2] = xq[0]; zr[3] = xq[1];
            *(float4*)(smem + OFF_AT + row * 16) = ((const float4*)attr)[e];
            *(int*)(smem + OFF_VJ + row * 4) = vj;
        }
        __syncthreads();

        // ================= phase 2: MMA + fused epilogue =================
        const int wbase = wid * 64;
        const float fz = 0.0f;
        #pragma unroll 1
        for (int mt = 0; mt < 4; mt++) {
            const int r0 = wbase + mt * 16 + gID;
            const int r8 = r0 + 8;

            // A fragments (h fp16), all 4 k-steps
            uint32_t af[4][4];
            {
                const char* p0 = smem + OFF_H + r0 * HSTRIDE + tig * 4;
                const char* p8 = smem + OFF_H + r8 * HSTRIDE + tig * 4;
                #pragma unroll
                for (int ks = 0; ks < 4; ks++) {
                    af[ks][0] = *(const uint32_t*)(p0 + ks * 32);
                    af[ks][1] = *(const uint32_t*)(p8 + ks * 32);
                    af[ks][2] = *(const uint32_t*)(p0 + ks * 32 + 16);
                    af[ks][3] = *(const uint32_t*)(p8 + ks * 32 + 16);
                }
            }
            float z0[16], z1[16], at0[4], at1[4];
            {
                const float4* q0 = (const float4*)(smem + OFF_Z + r0 * 64);
                const float4* q1 = (const float4*)(smem + OFF_Z + r8 * 64);
                #pragma unroll
                for (int q = 0; q < 4; q++) {
                    float4 a = q0[q]; z0[4*q]=a.x; z0[4*q+1]=a.y; z0[4*q+2]=a.z; z0[4*q+3]=a.w;
                    float4 b = q1[q]; z1[4*q]=b.x; z1[4*q+1]=b.y; z1[4*q+2]=b.z; z1[4*q+3]=b.w;
                }
                float4 a = *(const float4*)(smem + OFF_AT + r0 * 16);
                at0[0]=a.x; at0[1]=a.y; at0[2]=a.z; at0[3]=a.w;
                float4 b = *(const float4*)(smem + OFF_AT + r8 * 16);
                at1[0]=b.x; at1[1]=b.y; at1[2]=b.z; at1[3]=b.w;
            }

            float acc0 = 0.f, acc1 = 0.f, acc2 = 0.f, acc3 = 0.f;

            #pragma unroll 4
            for (int nt = 0; nt < 64; nt++) {
                float d1[4], d2[4];
                const uint4* bp = (const uint4*)(smem + OFF_BP + (size_t)nt * 2048) + lane;
                {
                    uint4 b = bp[0];
                    mma_f16_z(d1, af[0][0], af[0][1], af[0][2], af[0][3], b.x, b.y, fz);
                    mma_f16_z(d2, af[0][0], af[0][1], af[0][2], af[0][3], b.z, b.w, fz);
                }
                #pragma unroll
                for (int ks = 1; ks < 4; ks++) {
                    uint4 b = bp[ks * 32];
                    mma_f16(d1, af[ks][0], af[ks][1], af[ks][2], af[ks][3], b.x, b.y);
                    mma_f16(d2, af[ks][0], af[ks][1], af[ks][2], af[ks][3], b.z, b.w);
                }
                const int a = nt >> 4, b = nt & 15;
                const float c0 = at0[a] * z0[b];
                const float c1 = at1[a] * z1[b];
                acc0 += c0 * (d1[0] + d2[0]);
                acc1 += c0 * (d1[1] + d2[1]);
                acc2 += c1 * (d1[2] + d2[2]);
                acc3 += c1 * (d1[3] + d2[3]);
            }

            const float sc = 1.0f / 64.0f;
            acc0 *= sc; acc1 *= sc; acc2 *= sc; acc3 *= sc;
            const int e0 = tile * TILE_M + r0;
            const int e1 = tile * TILE_M + r8;
            *(float2*)(edge_out + (size_t)e0 * 8 + 2 * tig) = make_float2(acc0, acc1);
            *(float2*)(edge_out + (size_t)e1 * 8 + 2 * tig) = make_float2(acc2, acc3);
            const int vj0 = *(const int*)(smem + OFF_VJ + r0 * 4);
            const int vj1 = *(const int*)(smem + OFF_VJ + r8 * 4);
            atomicAdd(g_esum + (size_t)vj0 * 8 + 2 * tig,     acc0);
            atomicAdd(g_esum + (size_t)vj0 * 8 + 2 * tig + 1, acc1);
            atomicAdd(g_esum + (size_t)vj1 * 8 + 2 * tig,     acc2);
            atomicAdd(g_esum + (size_t)vj1 * 8 + 2 * tig + 1, acc3);
        }
        __syncthreads();   // protect h/z staging reuse next tile
    }
}

__global__ __launch_bounds__(256)
void node_kernel(const float* __restrict__ x,
                 const float* __restrict__ w_node,
                 float*       __restrict__ x_out)
{
    __shared__ float swn[1024];   // [a][b][k]
    for (int idx = threadIdx.x; idx < 1024; idx += blockDim.x)
        swn[idx] = w_node[idx];
    __syncthreads();

    int n = blockIdx.x * blockDim.x + threadIdx.x;
    if (n >= N_NODES) return;

    float xv[8], ev[8];
    {
        const float4* xp = (const float4*)(x + (size_t)n * 8);
        float4 t0 = xp[0], t1 = xp[1];
        xv[0]=t0.x; xv[1]=t0.y; xv[2]=t0.z; xv[3]=t0.w;
        xv[4]=t1.x; xv[5]=t1.y; xv[6]=t1.z; xv[7]=t1.w;
        const float4* epp = (const float4*)(g_esum + (size_t)n * 8);
        float4 u0 = epp[0], u1 = epp[1];
        ev[0]=u0.x; ev[1]=u0.y; ev[2]=u0.z; ev[3]=u0.w;
        ev[4]=u1.x; ev[5]=u1.y; ev[6]=u1.z; ev[7]=u1.w;
    }

    float acc[16];
    #pragma unroll
    for (int k = 0; k < 16; k++) acc[k] = 0.0f;

    const float4* w4 = (const float4*)swn;
    #pragma unroll
    for (int a = 0; a < 8; a++) {
        #pragma unroll
        for (int b = 0; b < 8; b++) {
            float p = xv[a] * ev[b];
            int base = a * 32 + b * 4;
            float4 q0 = w4[base], q1 = w4[base+1], q2 = w4[base+2], q3 = w4[base+3];
            acc[0]+=p*q0.x;  acc[1]+=p*q0.y;  acc[2]+=p*q0.z;  acc[3]+=p*q0.w;
            acc[4]+=p*q1.x;  acc[5]+=p*q1.y;  acc[6]+=p*q1.z;  acc[7]+=p*q1.w;
            acc[8]+=p*q2.x;  acc[9]+=p*q2.y;  acc[10]+=p*q2.z; acc[11]+=p*q2.w;
            acc[12]+=p*q3.x; acc[13]+=p*q3.y; acc[14]+=p*q3.z; acc[15]+=p*q3.w;
        }
    }

    const float sc = 0.125f;
    float4* op = (float4*)(x_out + (size_t)n * 16);
    op[0] = make_float4(acc[0]*sc,  acc[1]*sc,  acc[2]*sc,  acc[3]*sc);
    op[1] = make_float4(acc[4]*sc,  acc[5]*sc,  acc[6]*sc,  acc[7]*sc);
    op[2] = make_float4(acc[8]*sc,  acc[9]*sc,  acc[10]*sc, acc[11]*sc);
    op[3] = make_float4(acc[12]*sc, acc[13]*sc, acc[14]*sc, acc[15]*sc);
}

extern "C" void kernel_launch(void* const* d_in, const int* in_sizes, int n_in,
                              void* d_out, int out_size)
{
    const float* x    = (const float*)d_in[0];
    const int*   ei   = (const int*)  d_in[1];
    const float* attr = (const float*)d_in[2];
    const float* emb  = (const float*)d_in[3];
    const float* w1   = (const float*)d_in[4];
    const float* w2   = (const float*)d_in[5];
    const float* wn   = (const float*)d_in[6];

    float* out      = (float*)d_out;
    float* x_out    = out;                    // [N, 16]
    float* edge_out = out + N_NODES * 16;     // [E, 8]

    static int attr_set = 0;
    if (!attr_set) {
        cudaFuncSetAttribute(edge_kernel,
                             cudaFuncAttributeMaxDynamicSharedMemorySize,
                             SMEM_TOTAL);
        attr_set = 1;
    }

    zero_esum_kernel<<<(N_NODES * 8 + 511) / 512, 512>>>();
    edge_kernel<<<148, 128, SMEM_TOTAL>>>(x, ei, attr, emb, w1, w2, edge_out);
    node_kernel<<<(N_NODES + 255) / 256, 256>>>(x, wn, x_out);
}

// round 6
// speedup vs baseline: 2.9759x; 1.1824x over previous
#include <cuda_runtime.h>
#include <cuda_fp16.h>
#include <cstdint>

#define N_NODES 50000
#define N_EDGES 800000
#define TILE_M  256
#define NTILES  (N_EDGES / TILE_M)   // 3125

#define HSTRIDE 136                   // h row pitch in bytes (64 fp16 = 128B + 8 pad)

// ---- smem layout (bytes) ----
// BP entry (nt, kpair, lane): 16B = { ks=2*kpair : (k0,k0+1),(k0+8,k0+9) | ks=2*kpair+1 : same }
#define OFF_BP   0                                  // 64nt * 2kpair * 32lane * 16B = 64K
#define OFF_H    65536                              // 256 rows * HSTRIDE (h in fp16)
#define OFF_Z    (OFF_H  + 256*HSTRIDE)             // 256 * 16 f32
#define OFF_AT   (OFF_Z  + 256*64)                  // 256 * 4 f32
#define OFF_VJ   (OFF_AT + 256*16)                  // 256 int
#define OFF_W1T  (OFF_VJ + 256*4)                   // 64*16 f32 transposed
#define SMEM_TOTAL (OFF_W1T + 4096)                 // ~126 KB

__device__ float g_esum[N_NODES * 8];

__global__ void zero_esum_kernel() {
    int i = blockIdx.x * blockDim.x + threadIdx.x;
    if (i < N_NODES * 8) g_esum[i] = 0.0f;
}

// pack two f32 -> f16x2 (first arg -> low half)
__device__ __forceinline__ uint32_t pack_f16x2(float lo, float hi) {
    uint32_t r;
    asm("cvt.rn.f16x2.f32 %0, %1, %2;" : "=r"(r) : "f"(hi), "f"(lo));
    return r;
}

__device__ __forceinline__ void mma_f16(float d[4],
                                        uint32_t a0, uint32_t a1, uint32_t a2, uint32_t a3,
                                        uint32_t b0, uint32_t b1) {
    asm volatile(
        "mma.sync.aligned.m16n8k16.row.col.f32.f16.f16.f32 "
        "{%0,%1,%2,%3}, {%4,%5,%6,%7}, {%8,%9}, {%0,%1,%2,%3};"
        : "+f"(d[0]), "+f"(d[1]), "+f"(d[2]), "+f"(d[3])
        : "r"(a0), "r"(a1), "r"(a2), "r"(a3), "r"(b0), "r"(b1));
}

// first k-step: C = 0 (no accumulator zero-MOVs)
__device__ __forceinline__ void mma_f16_z(float d[4],
                                          uint32_t a0, uint32_t a1, uint32_t a2, uint32_t a3,
                                          uint32_t b0, uint32_t b1, float zz) {
    asm volatile(
        "mma.sync.aligned.m16n8k16.row.col.f32.f16.f16.f32 "
        "{%0,%1,%2,%3}, {%4,%5,%6,%7}, {%8,%9}, {%10,%10,%10,%10};"
        : "=f"(d[0]), "=f"(d[1]), "=f"(d[2]), "=f"(d[3])
        : "r"(a0), "r"(a1), "r"(a2), "r"(a3), "r"(b0), "r"(b1), "f"(zz));
}

__global__ __launch_bounds__(128, 1)
void edge_kernel(const float* __restrict__ x,
                 const int*   __restrict__ ei,
                 const float* __restrict__ attr,
                 const float* __restrict__ emb,
                 const float* __restrict__ w1,
                 const float* __restrict__ w2,
                 float*       __restrict__ edge_out)
{
    extern __shared__ char smem[];
    const int tid  = threadIdx.x;
    const int lane = tid & 31;
    const int gID  = lane >> 2;
    const int tig  = lane & 3;
    const int wid  = tid >> 5;

    float* sw1t = (float*)(smem + OFF_W1T);
    for (int idx = tid; idx < 1024; idx += blockDim.x) {
        int c = idx >> 4, d = idx & 15;
        sw1t[idx] = w1[d * 64 + c];
    }
    // ---- preload W2 as packed single-fp16 B fragments ----
    // entry idx = nt*64 + kpair*32 + lane ; n = nt*8 + lane/4
    // kpair covers ks = 2*kpair (first 8B) and ks = 2*kpair+1 (second 8B)
    // per ks: k0 = ks*16 + (lane%4)*2 ; 8B = { (k0,k0+1) , (k0+8,k0+9) }
    for (int ent = tid; ent < 4096; ent += blockDim.x) {
        int l  = ent & 31;
        int kp = (ent >> 5) & 1;
        int nt = ent >> 6;
        int n  = nt * 8 + (l >> 2);
        uint4 pk;
        #pragma unroll
        for (int half = 0; half < 2; half++) {
            int ks = kp * 2 + half;
            int k0 = ks * 16 + (l & 3) * 2;
            float v0 = w2[(k0    ) * 512 + n];
            float v1 = w2[(k0 + 1) * 512 + n];
            float v2 = w2[(k0 + 8) * 512 + n];
            float v3 = w2[(k0 + 9) * 512 + n];
            if (half == 0) { pk.x = pack_f16x2(v0, v1); pk.y = pack_f16x2(v2, v3); }
            else           { pk.z = pack_f16x2(v0, v1); pk.w = pack_f16x2(v2, v3); }
        }
        *(uint4*)(smem + OFF_BP + (size_t)ent * 16) = pk;
    }
    __syncthreads();

    for (int tile = blockIdx.x; tile < NTILES; tile += gridDim.x) {
        // ================= phase 1: per-edge h + staging =================
        #pragma unroll
        for (int s = 0; s < 2; s++) {
            const int row = tid + s * 128;
            const int e   = tile * TILE_M + row;

            float em[16];
            {
                const float4* ep = (const float4*)(emb + (size_t)e * 16);
                #pragma unroll
                for (int q = 0; q < 4; q++) {
                    float4 t = ep[q];
                    em[4*q]=t.x; em[4*q+1]=t.y; em[4*q+2]=t.z; em[4*q+3]=t.w;
                }
            }
            char* hrow = smem + OFF_H + row * HSTRIDE;
            #pragma unroll 4
            for (int c = 0; c < 64; c += 2) {
                float sa = 0.f, sb = 0.f;
                const float* wa = sw1t + c * 16;
                const float* wb = wa + 16;
                #pragma unroll
                for (int d = 0; d < 16; d++) {
                    sa += em[d] * wa[d];
                    sb += em[d] * wb[d];
                }
                sa *= 0.25f; sb *= 0.25f;
                float ha = sa / (1.0f + __expf(-sa));
                float hb = sb / (1.0f + __expf(-sb));
                *(uint32_t*)(hrow + c * 2) = pack_f16x2(ha, hb);
            }

            const int vi = ei[e];
            const int vj = ei[N_EDGES + e];
            float4* zr = (float4*)(smem + OFF_Z + row * 64);
            const float4* xp = (const float4*)(x + (size_t)vi * 8);
            zr[0] = xp[0]; zr[1] = xp[1];
            const float4* xq = (const float4*)(x + (size_t)vj * 8);
            zr[2] = xq[0]; zr[3] = xq[1];
            *(float4*)(smem + OFF_AT + row * 16) = ((const float4*)attr)[e];
            *(int*)(smem + OFF_VJ + row * 4) = vj;
        }
        __syncthreads();

        // ================= phase 2: MMA + fused epilogue =================
        const int wbase = wid * 64;
        const float fz = 0.0f;
        #pragma unroll 1
        for (int mt = 0; mt < 4; mt++) {
            const int r0 = wbase + mt * 16 + gID;
            const int r8 = r0 + 8;

            // A fragments (h fp16), all 4 k-steps
            uint32_t af[4][4];
            {
                const char* p0 = smem + OFF_H + r0 * HSTRIDE + tig * 4;
                const char* p8 = smem + OFF_H + r8 * HSTRIDE + tig * 4;
                #pragma unroll
                for (int ks = 0; ks < 4; ks++) {
                    af[ks][0] = *(const uint32_t*)(p0 + ks * 32);
                    af[ks][1] = *(const uint32_t*)(p8 + ks * 32);
                    af[ks][2] = *(const uint32_t*)(p0 + ks * 32 + 16);
                    af[ks][3] = *(const uint32_t*)(p8 + ks * 32 + 16);
                }
            }
            float z0[16], z1[16], at0[4], at1[4];
            {
                const float4* q0 = (const float4*)(smem + OFF_Z + r0 * 64);
                const float4* q1 = (const float4*)(smem + OFF_Z + r8 * 64);
                #pragma unroll
                for (int q = 0; q < 4; q++) {
                    float4 a = q0[q]; z0[4*q]=a.x; z0[4*q+1]=a.y; z0[4*q+2]=a.z; z0[4*q+3]=a.w;
                    float4 b = q1[q]; z1[4*q]=b.x; z1[4*q+1]=b.y; z1[4*q+2]=b.z; z1[4*q+3]=b.w;
                }
                float4 a = *(const float4*)(smem + OFF_AT + r0 * 16);
                at0[0]=a.x; at0[1]=a.y; at0[2]=a.z; at0[3]=a.w;
                float4 b = *(const float4*)(smem + OFF_AT + r8 * 16);
                at1[0]=b.x; at1[1]=b.y; at1[2]=b.z; at1[3]=b.w;
            }

            float acc0 = 0.f, acc1 = 0.f, acc2 = 0.f, acc3 = 0.f;

            #pragma unroll 4
            for (int nt = 0; nt < 64; nt++) {
                float d1[4];
                const uint4* bp = (const uint4*)(smem + OFF_BP + (size_t)nt * 1024) + lane;
                {
                    uint4 b01 = bp[0];        // ks0 (x,y), ks1 (z,w)
                    mma_f16_z(d1, af[0][0], af[0][1], af[0][2], af[0][3], b01.x, b01.y, fz);
                    mma_f16 (d1, af[1][0], af[1][1], af[1][2], af[1][3], b01.z, b01.w);
                }
                {
                    uint4 b23 = bp[32];       // ks2 (x,y), ks3 (z,w)
                    mma_f16 (d1, af[2][0], af[2][1], af[2][2], af[2][3], b23.x, b23.y);
                    mma_f16 (d1, af[3][0], af[3][1], af[3][2], af[3][3], b23.z, b23.w);
                }
                const int a = nt >> 4, b = nt & 15;
                const float c0 = at0[a] * z0[b];
                const float c1 = at1[a] * z1[b];
                acc0 += c0 * d1[0];
                acc1 += c0 * d1[1];
                acc2 += c1 * d1[2];
                acc3 += c1 * d1[3];
            }

            const float sc = 1.0f / 64.0f;
            acc0 *= sc; acc1 *= sc; acc2 *= sc; acc3 *= sc;
            const int e0 = tile * TILE_M + r0;
            const int e1 = tile * TILE_M + r8;
            *(float2*)(edge_out + (size_t)e0 * 8 + 2 * tig) = make_float2(acc0, acc1);
            *(float2*)(edge_out + (size_t)e1 * 8 + 2 * tig) = make_float2(acc2, acc3);
            const int vj0 = *(const int*)(smem + OFF_VJ + r0 * 4);
            const int vj1 = *(const int*)(smem + OFF_VJ + r8 * 4);
            atomicAdd(g_esum + (size_t)vj0 * 8 + 2 * tig,     acc0);
            atomicAdd(g_esum + (size_t)vj0 * 8 + 2 * tig + 1, acc1);
            atomicAdd(g_esum + (size_t)vj1 * 8 + 2 * tig,     acc2);
            atomicAdd(g_esum + (size_t)vj1 * 8 + 2 * tig + 1, acc3);
        }
        __syncthreads();   // protect h/z staging reuse next tile
    }
}

__global__ __launch_bounds__(256)
void node_kernel(const float* __restrict__ x,
                 const float* __restrict__ w_node,
                 float*       __restrict__ x_out)
{
    __shared__ float swn[1024];   // [a][b][k]
    for (int idx = threadIdx.x; idx < 1024; idx += blockDim.x)
        swn[idx] = w_node[idx];
    __syncthreads();

    int n = blockIdx.x * blockDim.x + threadIdx.x;
    if (n >= N_NODES) return;

    float xv[8], ev[8];
    {
        const float4* xp = (const float4*)(x + (size_t)n * 8);
        float4 t0 = xp[0], t1 = xp[1];
        xv[0]=t0.x; xv[1]=t0.y; xv[2]=t0.z; xv[3]=t0.w;
        xv[4]=t1.x; xv[5]=t1.y; xv[6]=t1.z; xv[7]=t1.w;
        const float4* epp = (const float4*)(g_esum + (size_t)n * 8);
        float4 u0 = epp[0], u1 = epp[1];
        ev[0]=u0.x; ev[1]=u0.y; ev[2]=u0.z; ev[3]=u0.w;
        ev[4]=u1.x; ev[5]=u1.y; ev[6]=u1.z; ev[7]=u1.w;
    }

    float acc[16];
    #pragma unroll
    for (int k = 0; k < 16; k++) acc[k] = 0.0f;

    const float4* w4 = (const float4*)swn;
    #pragma unroll
    for (int a = 0; a < 8; a++) {
        #pragma unroll
        for (int b = 0; b < 8; b++) {
            float p = xv[a] * ev[b];
            int base = a * 32 + b * 4;
            float4 q0 = w4[base], q1 = w4[base+1], q2 = w4[base+2], q3 = w4[base+3];
            acc[0]+=p*q0.x;  acc[1]+=p*q0.y;  acc[2]+=p*q0.z;  acc[3]+=p*q0.w;
            acc[4]+=p*q1.x;  acc[5]+=p*q1.y;  acc[6]+=p*q1.z;  acc[7]+=p*q1.w;
            acc[8]+=p*q2.x;  acc[9]+=p*q2.y;  acc[10]+=p*q2.z; acc[11]+=p*q2.w;
            acc[12]+=p*q3.x; acc[13]+=p*q3.y; acc[14]+=p*q3.z; acc[15]+=p*q3.w;
        }
    }

    const float sc = 0.125f;
    float4* op = (float4*)(x_out + (size_t)n * 16);
    op[0] = make_float4(acc[0]*sc,  acc[1]*sc,  acc[2]*sc,  acc[3]*sc);
    op[1] = make_float4(acc[4]*sc,  acc[5]*sc,  acc[6]*sc,  acc[7]*sc);
    op[2] = make_float4(acc[8]*sc,  acc[9]*sc,  acc[10]*sc, acc[11]*sc);
    op[3] = make_float4(acc[12]*sc, acc[13]*sc, acc[14]*sc, acc[15]*sc);
}

extern "C" void kernel_launch(void* const* d_in, const int* in_sizes, int n_in,
                              void* d_out, int out_size)
{
    const float* x    = (const float*)d_in[0];
    const int*   ei   = (const int*)  d_in[1];
    const float* attr = (const float*)d_in[2];
    const float* emb  = (const float*)d_in[3];
    const float* w1   = (const float*)d_in[4];
    const float* w2   = (const float*)d_in[5];
    const float* wn   = (const float*)d_in[6];

    float* out      = (float*)d_out;
    float* x_out    = out;                    // [N, 16]
    float* edge_out = out + N_NODES * 16;     // [E, 8]

    static int attr_set = 0;
    if (!attr_set) {
        cudaFuncSetAttribute(edge_kernel,
                             cudaFuncAttributeMaxDynamicSharedMemorySize,
                             SMEM_TOTAL);
        attr_set = 1;
    }

    zero_esum_kernel<<<(N_NODES * 8 + 511) / 512, 512>>>();
    edge_kernel<<<148, 128, SMEM_TOTAL>>>(x, ei, attr, emb, w1, w2, edge_out);
    node_kernel<<<(N_NODES + 255) / 256, 256>>>(x, wn, x_out);
}

// round 7
// speedup vs baseline: 5.9049x; 1.9843x over previous
#include <cuda_runtime.h>
#include <cuda_fp16.h>
#include <cstdint>

#define N_NODES 50000
#define N_EDGES 800000
#define TILE_M  256
#define NTILES  (N_EDGES / TILE_M)   // 3125

// ---- smem layout (bytes) ----
// BP entry (nt, kpair, lane): 16B = { ks=2*kpair : (k0,k0+1),(k0+8,k0+9) | ks=2*kpair+1 : same }
#define OFF_BP   0                               // 64nt * 2kpair * 32lane * 16B = 64K
#define OFF_ZS   65536                           // 2 bufs * 256 rows * 80B (z[16] + at[4])
#define OFF_VJ   (OFF_ZS + 2*256*80)             // 2 bufs * 256 int
#define SMEM_TOTAL (OFF_VJ + 2*256*4)            // 108544 B

__device__ float g_esum[N_NODES * 8];

__global__ void zero_esum_kernel() {
    int i = blockIdx.x * blockDim.x + threadIdx.x;
    if (i < N_NODES * 8) g_esum[i] = 0.0f;
}

// pack two f32 -> f16x2 (first arg -> low half)
__device__ __forceinline__ uint32_t pack_f16x2(float lo, float hi) {
    uint32_t r;
    asm("cvt.rn.f16x2.f32 %0, %1, %2;" : "=r"(r) : "f"(hi), "f"(lo));
    return r;
}

__device__ __forceinline__ void mma_f16(float d[4],
                                        uint32_t a0, uint32_t a1, uint32_t a2, uint32_t a3,
                                        uint32_t b0, uint32_t b1) {
    asm volatile(
        "mma.sync.aligned.m16n8k16.row.col.f32.f16.f16.f32 "
        "{%0,%1,%2,%3}, {%4,%5,%6,%7}, {%8,%9}, {%0,%1,%2,%3};"
        : "+f"(d[0]), "+f"(d[1]), "+f"(d[2]), "+f"(d[3])
        : "r"(a0), "r"(a1), "r"(a2), "r"(a3), "r"(b0), "r"(b1));
}

// C = 0 variant (no accumulator zeroing MOVs)
__device__ __forceinline__ void mma_f16_z(float d[4],
                                          uint32_t a0, uint32_t a1, uint32_t a2, uint32_t a3,
                                          uint32_t b0, uint32_t b1, float zz) {
    asm volatile(
        "mma.sync.aligned.m16n8k16.row.col.f32.f16.f16.f32 "
        "{%0,%1,%2,%3}, {%4,%5,%6,%7}, {%8,%9}, {%10,%10,%10,%10};"
        : "=f"(d[0]), "=f"(d[1]), "=f"(d[2]), "=f"(d[3])
        : "r"(a0), "r"(a1), "r"(a2), "r"(a3), "r"(b0), "r"(b1), "f"(zz));
}

__device__ __forceinline__ float fsilu(float s) {
    return __fdividef(s, 1.0f + __expf(-s));
}

__device__ __forceinline__ void red_addf(float* p, float v) {
    asm volatile("red.global.add.f32 [%0], %1;" :: "l"(p), "f"(v) : "memory");
}

__global__ __launch_bounds__(128, 1)
void edge_kernel(const float* __restrict__ x,
                 const int*   __restrict__ ei,
                 const float* __restrict__ attr,
                 const float* __restrict__ emb,
                 const float* __restrict__ w1,
                 const float* __restrict__ w2,
                 float*       __restrict__ edge_out)
{
    extern __shared__ char smem[];
    const int tid  = threadIdx.x;
    const int lane = tid & 31;
    const int gID  = lane >> 2;
    const int tig  = lane & 3;
    const int wid  = tid >> 5;

    // ---- w1 B-fragments in registers, fp16 hi/lo split (persist whole kernel)
    // phase-1 GEMM: s[row, c] = sum_d emb[row,d] * w1[d,c]; B[k=d][n=c]
    uint32_t w1h[8][2], w1l[8][2];
    #pragma unroll
    for (int nt = 0; nt < 8; nt++) {
        const int c = nt * 8 + gID;
        #pragma unroll
        for (int jj = 0; jj < 2; jj++) {
            const int d0 = 2 * tig + jj * 8;
            float v0 = w1[d0 * 64 + c];
            float v1 = w1[(d0 + 1) * 64 + c];
            float h0 = __half2float(__float2half_rn(v0));
            float h1 = __half2float(__float2half_rn(v1));
            w1h[nt][jj] = pack_f16x2(h0, h1);
            w1l[nt][jj] = pack_f16x2(v0 - h0, v1 - h1);
        }
    }

    // ---- preload W2 as packed single-fp16 B fragments (as R6) ----
    for (int ent = tid; ent < 4096; ent += blockDim.x) {
        int l  = ent & 31;
        int kp = (ent >> 5) & 1;
        int nt = ent >> 6;
        int n  = nt * 8 + (l >> 2);
        uint4 pk;
        #pragma unroll
        for (int half = 0; half < 2; half++) {
            int ks = kp * 2 + half;
            int k0 = ks * 16 + (l & 3) * 2;
            float v0 = w2[(k0    ) * 512 + n];
            float v1 = w2[(k0 + 1) * 512 + n];
            float v2 = w2[(k0 + 8) * 512 + n];
            float v3 = w2[(k0 + 9) * 512 + n];
            if (half == 0) { pk.x = pack_f16x2(v0, v1); pk.y = pack_f16x2(v2, v3); }
            else           { pk.z = pack_f16x2(v0, v1); pk.w = pack_f16x2(v2, v3); }
        }
        *(uint4*)(smem + OFF_BP + (size_t)ent * 16) = pk;
    }
    __syncthreads();

    int it = 0;
    for (int tile = blockIdx.x; tile < NTILES; tile += gridDim.x, it++) {
        const int buf = it & 1;

        // ---- staging: z (x[i]|x[j]) + attr + vj, 80B row stride, double-buffered
        #pragma unroll
        for (int s = 0; s < 2; s++) {
            const int row = tid + s * 128;
            const int e   = tile * TILE_M + row;
            const int vi = ei[e];
            const int vj = ei[N_EDGES + e];
            float4* zr = (float4*)(smem + OFF_ZS + (size_t)(buf * 256 + row) * 80);
            const float4* xp = (const float4*)(x + (size_t)vi * 8);
            zr[0] = xp[0]; zr[1] = xp[1];
            const float4* xq = (const float4*)(x + (size_t)vj * 8);
            zr[2] = xq[0]; zr[3] = xq[1];
            zr[4] = ((const float4*)attr)[e];
            *(int*)(smem + OFF_VJ + (size_t)(buf * 256 + row) * 4) = vj;
        }
        __syncthreads();

        const int wbase = wid * 64;
        const float fz = 0.0f;
        #pragma unroll 1
        for (int mt = 0; mt < 4; mt++) {
            const int r0 = wbase + mt * 16 + gID;
            const int r8 = r0 + 8;
            const int e0 = tile * TILE_M + r0;
            const int e8 = tile * TILE_M + r8;

            // ---- emb A-fragments from gmem, fp16 hi/lo split
            uint32_t ahi[4], alo[4];
            {
                const float2* p0 = (const float2*)(emb + (size_t)e0 * 16);
                const float2* p8 = (const float2*)(emb + (size_t)e8 * 16);
                float2 v0l = p0[tig], v0h = p0[tig + 4];
                float2 v8l = p8[tig], v8h = p8[tig + 4];
                float h;
                float2 t;
                t = v0l; h = __half2float(__float2half_rn(t.x));
                float hx0 = h, lx0 = t.x - h;
                h = __half2float(__float2half_rn(t.y));
                float hy0 = h, ly0 = t.y - h;
                ahi[0] = pack_f16x2(hx0, hy0); alo[0] = pack_f16x2(lx0, ly0);
                t = v8l; h = __half2float(__float2half_rn(t.x));
                float hx1 = h, lx1 = t.x - h;
                h = __half2float(__float2half_rn(t.y));
                float hy1 = h, ly1 = t.y - h;
                ahi[1] = pack_f16x2(hx1, hy1); alo[1] = pack_f16x2(lx1, ly1);
                t = v0h; h = __half2float(__float2half_rn(t.x));
                float hx2 = h, lx2 = t.x - h;
                h = __half2float(__float2half_rn(t.y));
                float hy2 = h, ly2 = t.y - h;
                ahi[2] = pack_f16x2(hx2, hy2); alo[2] = pack_f16x2(lx2, ly2);
                t = v8h; h = __half2float(__float2half_rn(t.x));
                float hx3 = h, lx3 = t.x - h;
                h = __half2float(__float2half_rn(t.y));
                float hy3 = h, ly3 = t.y - h;
                ahi[3] = pack_f16x2(hx3, hy3); alo[3] = pack_f16x2(lx3, ly3);
            }

            // ---- phase-1 MMA (3-pass exact) -> silu -> phase-2 A-fragments
            uint32_t af[4][4];
            #pragma unroll
            for (int ks = 0; ks < 4; ks++) {
                #pragma unroll
                for (int j = 0; j < 2; j++) {
                    const int nt = 2 * ks + j;
                    float dd[4];
                    mma_f16_z(dd, ahi[0], ahi[1], ahi[2], ahi[3], w1h[nt][0], w1h[nt][1], fz);
                    mma_f16 (dd, ahi[0], ahi[1], ahi[2], ahi[3], w1l[nt][0], w1l[nt][1]);
                    mma_f16 (dd, alo[0], alo[1], alo[2], alo[3], w1h[nt][0], w1h[nt][1]);
                    float h0 = fsilu(dd[0] * 0.25f);
                    float h1 = fsilu(dd[1] * 0.25f);
                    float h2 = fsilu(dd[2] * 0.25f);
                    float h3 = fsilu(dd[3] * 0.25f);
                    af[ks][2 * j]     = pack_f16x2(h0, h1);   // (r0, k-cols)
                    af[ks][2 * j + 1] = pack_f16x2(h2, h3);   // (r8, k-cols)
                }
            }

            // ---- z / attr from staged smem (conflict-free 80B stride)
            float z0[16], z1[16], at0[4], at1[4];
            {
                const float4* q0 = (const float4*)(smem + OFF_ZS + (size_t)(buf * 256 + r0) * 80);
                const float4* q1 = (const float4*)(smem + OFF_ZS + (size_t)(buf * 256 + r8) * 80);
                #pragma unroll
                for (int q = 0; q < 4; q++) {
                    float4 a = q0[q]; z0[4*q]=a.x; z0[4*q+1]=a.y; z0[4*q+2]=a.z; z0[4*q+3]=a.w;
                    float4 b = q1[q]; z1[4*q]=b.x; z1[4*q+1]=b.y; z1[4*q+2]=b.z; z1[4*q+3]=b.w;
                }
                float4 a = q0[4]; at0[0]=a.x; at0[1]=a.y; at0[2]=a.z; at0[3]=a.w;
                float4 b = q1[4]; at1[0]=b.x; at1[1]=b.y; at1[2]=b.z; at1[3]=b.w;
            }

            float acc0 = 0.f, acc1 = 0.f, acc2 = 0.f, acc3 = 0.f;

            #pragma unroll
            for (int nt = 0; nt < 64; nt++) {      // FULL unroll: const z/at indices
                float d1[4];
                const uint4* bp = (const uint4*)(smem + OFF_BP + (size_t)nt * 1024) + lane;
                {
                    uint4 b01 = bp[0];        // ks0 (x,y), ks1 (z,w)
                    mma_f16_z(d1, af[0][0], af[0][1], af[0][2], af[0][3], b01.x, b01.y, fz);
                    mma_f16 (d1, af[1][0], af[1][1], af[1][2], af[1][3], b01.z, b01.w);
                }
                {
                    uint4 b23 = bp[32];       // ks2 (x,y), ks3 (z,w)
                    mma_f16 (d1, af[2][0], af[2][1], af[2][2], af[2][3], b23.x, b23.y);
                    mma_f16 (d1, af[3][0], af[3][1], af[3][2], af[3][3], b23.z, b23.w);
                }
                const float c0 = at0[nt >> 4] * z0[nt & 15];
                const float c1 = at1[nt >> 4] * z1[nt & 15];
                acc0 += c0 * d1[0];
                acc1 += c0 * d1[1];
                acc2 += c1 * d1[2];
                acc3 += c1 * d1[3];
            }

            const float sc = 1.0f / 64.0f;
            acc0 *= sc; acc1 *= sc; acc2 *= sc; acc3 *= sc;
            *(float2*)(edge_out + (size_t)e0 * 8 + 2 * tig) = make_float2(acc0, acc1);
            *(float2*)(edge_out + (size_t)e8 * 8 + 2 * tig) = make_float2(acc2, acc3);
            const int vj0 = *(const int*)(smem + OFF_VJ + (size_t)(buf * 256 + r0) * 4);
            const int vj1 = *(const int*)(smem + OFF_VJ + (size_t)(buf * 256 + r8) * 4);
            red_addf(g_esum + (size_t)vj0 * 8 + 2 * tig,     acc0);
            red_addf(g_esum + (size_t)vj0 * 8 + 2 * tig + 1, acc1);
            red_addf(g_esum + (size_t)vj1 * 8 + 2 * tig,     acc2);
            red_addf(g_esum + (size_t)vj1 * 8 + 2 * tig + 1, acc3);
        }
        // no trailing sync: next iteration stages the other buffer
    }
}

__global__ __launch_bounds__(256)
void node_kernel(const float* __restrict__ x,
                 const float* __restrict__ w_node,
                 float*       __restrict__ x_out)
{
    __shared__ float swn[1024];   // [a][b][k]
    for (int idx = threadIdx.x; idx < 1024; idx += blockDim.x)
        swn[idx] = w_node[idx];
    __syncthreads();

    int n = blockIdx.x * blockDim.x + threadIdx.x;
    if (n >= N_NODES) return;

    float xv[8], ev[8];
    {
        const float4* xp = (const float4*)(x + (size_t)n * 8);
        float4 t0 = xp[0], t1 = xp[1];
        xv[0]=t0.x; xv[1]=t0.y; xv[2]=t0.z; xv[3]=t0.w;
        xv[4]=t1.x; xv[5]=t1.y; xv[6]=t1.z; xv[7]=t1.w;
        const float4* epp = (const float4*)(g_esum + (size_t)n * 8);
        float4 u0 = epp[0], u1 = epp[1];
        ev[0]=u0.x; ev[1]=u0.y; ev[2]=u0.z; ev[3]=u0.w;
        ev[4]=u1.x; ev[5]=u1.y; ev[6]=u1.z; ev[7]=u1.w;
    }

    float acc[16];
    #pragma unroll
    for (int k = 0; k < 16; k++) acc[k] = 0.0f;

    const float4* w4 = (const float4*)swn;
    #pragma unroll
    for (int a = 0; a < 8; a++) {
        #pragma unroll
        for (int b = 0; b < 8; b++) {
            float p = xv[a] * ev[b];
            int base = a * 32 + b * 4;
            float4 q0 = w4[base], q1 = w4[base+1], q2 = w4[base+2], q3 = w4[base+3];
            acc[0]+=p*q0.x;  acc[1]+=p*q0.y;  acc[2]+=p*q0.z;  acc[3]+=p*q0.w;
            acc[4]+=p*q1.x;  acc[5]+=p*q1.y;  acc[6]+=p*q1.z;  acc[7]+=p*q1.w;
            acc[8]+=p*q2.x;  acc[9]+=p*q2.y;  acc[10]+=p*q2.z; acc[11]+=p*q2.w;
            acc[12]+=p*q3.x; acc[13]+=p*q3.y; acc[14]+=p*q3.z; acc[15]+=p*q3.w;
        }
    }

    const float sc = 0.125f;
    float4* op = (float4*)(x_out + (size_t)n * 16);
    op[0] = make_float4(acc[0]*sc,  acc[1]*sc,  acc[2]*sc,  acc[3]*sc);
    op[1] = make_float4(acc[4]*sc,  acc[5]*sc,  acc[6]*sc,  acc[7]*sc);
    op[2] = make_float4(acc[8]*sc,  acc[9]*sc,  acc[10]*sc, acc[11]*sc);
    op[3] = make_float4(acc[12]*sc, acc[13]*sc, acc[14]*sc, acc[15]*sc);
}

extern "C" void kernel_launch(void* const* d_in, const int* in_sizes, int n_in,
                              void* d_out, int out_size)
{
    const float* x    = (const float*)d_in[0];
    const int*   ei   = (const int*)  d_in[1];
    const float* attr = (const float*)d_in[2];
    const float* emb  = (const float*)d_in[3];
    const float* w1   = (const float*)d_in[4];
    const float* w2   = (const float*)d_in[5];
    const float* wn   = (const float*)d_in[6];

    float* out      = (float*)d_out;
    float* x_out    = out;                    // [N, 16]
    float* edge_out = out + N_NODES * 16;     // [E, 8]

    static int attr_set = 0;
    if (!attr_set) {
        cudaFuncSetAttribute(edge_kernel,
                             cudaFuncAttributeMaxDynamicSharedMemorySize,
                             SMEM_TOTAL);
        attr_set = 1;
    }

    zero_esum_kernel<<<(N_NODES * 8 + 511) / 512, 512>>>();
    edge_kernel<<<148, 128, SMEM_TOTAL>>>(x, ei, attr, emb, w1, w2, edge_out);
    node_kernel<<<(N_NODES + 255) / 256, 256>>>(x, wn, x_out);
}

// round 8
// speedup vs baseline: 6.9228x; 1.1724x over previous
#include <cuda_runtime.h>
#include <cuda_fp16.h>
#include <cstdint>

#define N_NODES 50000
#define N_EDGES 800000
#define TILE_M  256
#define NTILES  (N_EDGES / TILE_M)   // 3125
#define THREADS 256

// ---- smem layout (bytes) ----
// BP entry (nt, kpair, lane): 16B = { ks=2*kpair : (k0,k0+1),(k0+8,k0+9) | ks=2*kpair+1 : same }
#define OFF_BP   0                               // 64nt * 2kpair * 32lane * 16B = 64K
#define OFF_ZS   65536                           // 2 bufs * 256 rows * 80B (z[16] + at[4])
#define OFF_VJ   (OFF_ZS + 2*256*80)             // 2 bufs * 256 int
#define SMEM_TOTAL (OFF_VJ + 2*256*4)            // 108544 B

__device__ float g_esum[N_NODES * 8];

__global__ void zero_esum_kernel() {
    int i = blockIdx.x * blockDim.x + threadIdx.x;
    if (i < N_NODES * 8) g_esum[i] = 0.0f;
}

// pack two f32 -> f16x2 (first arg -> low half)
__device__ __forceinline__ uint32_t pack_f16x2(float lo, float hi) {
    uint32_t r;
    asm("cvt.rn.f16x2.f32 %0, %1, %2;" : "=r"(r) : "f"(hi), "f"(lo));
    return r;
}

__device__ __forceinline__ void mma_f16(float d[4],
                                        uint32_t a0, uint32_t a1, uint32_t a2, uint32_t a3,
                                        uint32_t b0, uint32_t b1) {
    asm volatile(
        "mma.sync.aligned.m16n8k16.row.col.f32.f16.f16.f32 "
        "{%0,%1,%2,%3}, {%4,%5,%6,%7}, {%8,%9}, {%0,%1,%2,%3};"
        : "+f"(d[0]), "+f"(d[1]), "+f"(d[2]), "+f"(d[3])
        : "r"(a0), "r"(a1), "r"(a2), "r"(a3), "r"(b0), "r"(b1));
}

// C = 0 variant (no accumulator zeroing MOVs)
__device__ __forceinline__ void mma_f16_z(float d[4],
                                          uint32_t a0, uint32_t a1, uint32_t a2, uint32_t a3,
                                          uint32_t b0, uint32_t b1, float zz) {
    asm volatile(
        "mma.sync.aligned.m16n8k16.row.col.f32.f16.f16.f32 "
        "{%0,%1,%2,%3}, {%4,%5,%6,%7}, {%8,%9}, {%10,%10,%10,%10};"
        : "=f"(d[0]), "=f"(d[1]), "=f"(d[2]), "=f"(d[3])
        : "r"(a0), "r"(a1), "r"(a2), "r"(a3), "r"(b0), "r"(b1), "f"(zz));
}

__device__ __forceinline__ float fsilu(float s) {
    return __fdividef(s, 1.0f + __expf(-s));
}

__device__ __forceinline__ void red_addf(float* p, float v) {
    asm volatile("red.global.add.f32 [%0], %1;" :: "l"(p), "f"(v) : "memory");
}

__global__ __launch_bounds__(THREADS, 1)
void edge_kernel(const float* __restrict__ x,
                 const int*   __restrict__ ei,
                 const float* __restrict__ attr,
                 const float* __restrict__ emb,
                 const float* __restrict__ w1,
                 const float* __restrict__ w2,
                 float*       __restrict__ edge_out)
{
    extern __shared__ char smem[];
    const int tid  = threadIdx.x;
    const int lane = tid & 31;
    const int gID  = lane >> 2;
    const int tig  = lane & 3;
    const int wid  = tid >> 5;

    // ---- w1 B-fragments in registers, fp16 hi/lo split (persist whole kernel)
    uint32_t w1h[8][2], w1l[8][2];
    #pragma unroll
    for (int nt = 0; nt < 8; nt++) {
        const int c = nt * 8 + gID;
        #pragma unroll
        for (int jj = 0; jj < 2; jj++) {
            const int d0 = 2 * tig + jj * 8;
            float v0 = w1[d0 * 64 + c];
            float v1 = w1[(d0 + 1) * 64 + c];
            float h0 = __half2float(__float2half_rn(v0));
            float h1 = __half2float(__float2half_rn(v1));
            w1h[nt][jj] = pack_f16x2(h0, h1);
            w1l[nt][jj] = pack_f16x2(v0 - h0, v1 - h1);
        }
    }

    // ---- preload W2 as packed single-fp16 B fragments ----
    for (int ent = tid; ent < 4096; ent += THREADS) {
        int l  = ent & 31;
        int kp = (ent >> 5) & 1;
        int nt = ent >> 6;
        int n  = nt * 8 + (l >> 2);
        uint4 pk;
        #pragma unroll
        for (int half = 0; half < 2; half++) {
            int ks = kp * 2 + half;
            int k0 = ks * 16 + (l & 3) * 2;
            float v0 = w2[(k0    ) * 512 + n];
            float v1 = w2[(k0 + 1) * 512 + n];
            float v2 = w2[(k0 + 8) * 512 + n];
            float v3 = w2[(k0 + 9) * 512 + n];
            if (half == 0) { pk.x = pack_f16x2(v0, v1); pk.y = pack_f16x2(v2, v3); }
            else           { pk.z = pack_f16x2(v0, v1); pk.w = pack_f16x2(v2, v3); }
        }
        *(uint4*)(smem + OFF_BP + (size_t)ent * 16) = pk;
    }
    __syncthreads();

    int it = 0;
    for (int tile = blockIdx.x; tile < NTILES; tile += gridDim.x, it++) {
        const int buf = it & 1;

        // ---- staging: z (x[i]|x[j]) + attr + vj, 80B row stride, double-buffered
        {
            const int row = tid;
            const int e   = tile * TILE_M + row;
            const int vi = ei[e];
            const int vj = ei[N_EDGES + e];
            float4* zr = (float4*)(smem + OFF_ZS + (size_t)(buf * 256 + row) * 80);
            const float4* xp = (const float4*)(x + (size_t)vi * 8);
            zr[0] = xp[0]; zr[1] = xp[1];
            const float4* xq = (const float4*)(x + (size_t)vj * 8);
            zr[2] = xq[0]; zr[3] = xq[1];
            zr[4] = ((const float4*)attr)[e];
            *(int*)(smem + OFF_VJ + (size_t)(buf * 256 + row) * 4) = vj;
        }
        __syncthreads();

        const int wbase = wid * 32;           // 8 warps x 32 edge-rows
        const float fz = 0.0f;
        #pragma unroll 1
        for (int mt = 0; mt < 2; mt++) {
            const int r0 = wbase + mt * 16 + gID;
            const int r8 = r0 + 8;
            const int e0 = tile * TILE_M + r0;
            const int e8 = tile * TILE_M + r8;

            // ---- emb A-fragments from gmem, fp16 hi/lo split
            uint32_t ahi[4], alo[4];
            {
                const float2* p0 = (const float2*)(emb + (size_t)e0 * 16);
                const float2* p8 = (const float2*)(emb + (size_t)e8 * 16);
                float2 v[4];
                v[0] = p0[tig]; v[1] = p8[tig]; v[2] = p0[tig + 4]; v[3] = p8[tig + 4];
                #pragma unroll
                for (int q = 0; q < 4; q++) {
                    float hx = __half2float(__float2half_rn(v[q].x));
                    float hy = __half2float(__float2half_rn(v[q].y));
                    ahi[q] = pack_f16x2(hx, hy);
                    alo[q] = pack_f16x2(v[q].x - hx, v[q].y - hy);
                }
            }

            // ---- phase-1 MMA (3-pass exact) -> silu -> phase-2 A-fragments
            uint32_t af[4][4];
            #pragma unroll
            for (int ks = 0; ks < 4; ks++) {
                #pragma unroll
                for (int j = 0; j < 2; j++) {
                    const int nt = 2 * ks + j;
                    float dd[4];
                    mma_f16_z(dd, ahi[0], ahi[1], ahi[2], ahi[3], w1h[nt][0], w1h[nt][1], fz);
                    mma_f16 (dd, ahi[0], ahi[1], ahi[2], ahi[3], w1l[nt][0], w1l[nt][1]);
                    mma_f16 (dd, alo[0], alo[1], alo[2], alo[3], w1h[nt][0], w1h[nt][1]);
                    float h0 = fsilu(dd[0] * 0.25f);
                    float h1 = fsilu(dd[1] * 0.25f);
                    float h2 = fsilu(dd[2] * 0.25f);
                    float h3 = fsilu(dd[3] * 0.25f);
                    af[ks][2 * j]     = pack_f16x2(h0, h1);   // (r0, k-cols)
                    af[ks][2 * j + 1] = pack_f16x2(h2, h3);   // (r8, k-cols)
                }
            }

            // ---- z / attr from staged smem (conflict-free 80B stride)
            float z0[16], z1[16], at0[4], at1[4];
            {
                const float4* q0 = (const float4*)(smem + OFF_ZS + (size_t)(buf * 256 + r0) * 80);
                const float4* q1 = (const float4*)(smem + OFF_ZS + (size_t)(buf * 256 + r8) * 80);
                #pragma unroll
                for (int q = 0; q < 4; q++) {
                    float4 a = q0[q]; z0[4*q]=a.x; z0[4*q+1]=a.y; z0[4*q+2]=a.z; z0[4*q+3]=a.w;
                    float4 b = q1[q]; z1[4*q]=b.x; z1[4*q+1]=b.y; z1[4*q+2]=b.z; z1[4*q+3]=b.w;
                }
                float4 a = q0[4]; at0[0]=a.x; at0[1]=a.y; at0[2]=a.z; at0[3]=a.w;
                float4 b = q1[4]; at1[0]=b.x; at1[1]=b.y; at1[2]=b.z; at1[3]=b.w;
            }

            float acc0 = 0.f, acc1 = 0.f, acc2 = 0.f, acc3 = 0.f;

            #pragma unroll
            for (int nt = 0; nt < 64; nt++) {      // FULL unroll: const z/at indices
                float d1[4];
                const uint4* bp = (const uint4*)(smem + OFF_BP + (size_t)nt * 1024) + lane;
                {
                    uint4 b01 = bp[0];        // ks0 (x,y), ks1 (z,w)
                    mma_f16_z(d1, af[0][0], af[0][1], af[0][2], af[0][3], b01.x, b01.y, fz);
                    mma_f16 (d1, af[1][0], af[1][1], af[1][2], af[1][3], b01.z, b01.w);
                }
                {
                    uint4 b23 = bp[32];       // ks2 (x,y), ks3 (z,w)
                    mma_f16 (d1, af[2][0], af[2][1], af[2][2], af[2][3], b23.x, b23.y);
                    mma_f16 (d1, af[3][0], af[3][1], af[3][2], af[3][3], b23.z, b23.w);
                }
                const float c0 = at0[nt >> 4] * z0[nt & 15];
                const float c1 = at1[nt >> 4] * z1[nt & 15];
                acc0 += c0 * d1[0];
                acc1 += c0 * d1[1];
                acc2 += c1 * d1[2];
                acc3 += c1 * d1[3];
            }

            const float sc = 1.0f / 64.0f;
            acc0 *= sc; acc1 *= sc; acc2 *= sc; acc3 *= sc;
            *(float2*)(edge_out + (size_t)e0 * 8 + 2 * tig) = make_float2(acc0, acc1);
            *(float2*)(edge_out + (size_t)e8 * 8 + 2 * tig) = make_float2(acc2, acc3);
            const int vj0 = *(const int*)(smem + OFF_VJ + (size_t)(buf * 256 + r0) * 4);
            const int vj1 = *(const int*)(smem + OFF_VJ + (size_t)(buf * 256 + r8) * 4);
            red_addf(g_esum + (size_t)vj0 * 8 + 2 * tig,     acc0);
            red_addf(g_esum + (size_t)vj0 * 8 + 2 * tig + 1, acc1);
            red_addf(g_esum + (size_t)vj1 * 8 + 2 * tig,     acc2);
            red_addf(g_esum + (size_t)vj1 * 8 + 2 * tig + 1, acc3);
        }
        // no trailing sync: next iteration stages the other buffer
    }
}

__global__ __launch_bounds__(256)
void node_kernel(const float* __restrict__ x,
                 const float* __restrict__ w_node,
                 float*       __restrict__ x_out)
{
    __shared__ float swn[1024];   // [a][b][k]
    for (int idx = threadIdx.x; idx < 1024; idx += blockDim.x)
        swn[idx] = w_node[idx];
    __syncthreads();

    int n = blockIdx.x * blockDim.x + threadIdx.x;
    if (n >= N_NODES) return;

    float xv[8], ev[8];
    {
        const float4* xp = (const float4*)(x + (size_t)n * 8);
        float4 t0 = xp[0], t1 = xp[1];
        xv[0]=t0.x; xv[1]=t0.y; xv[2]=t0.z; xv[3]=t0.w;
        xv[4]=t1.x; xv[5]=t1.y; xv[6]=t1.z; xv[7]=t1.w;
        const float4* epp = (const float4*)(g_esum + (size_t)n * 8);
        float4 u0 = epp[0], u1 = epp[1];
        ev[0]=u0.x; ev[1]=u0.y; ev[2]=u0.z; ev[3]=u0.w;
        ev[4]=u1.x; ev[5]=u1.y; ev[6]=u1.z; ev[7]=u1.w;
    }

    float acc[16];
    #pragma unroll
    for (int k = 0; k < 16; k++) acc[k] = 0.0f;

    const float4* w4 = (const float4*)swn;
    #pragma unroll
    for (int a = 0; a < 8; a++) {
        #pragma unroll
        for (int b = 0; b < 8; b++) {
            float p = xv[a] * ev[b];
            int base = a * 32 + b * 4;
            float4 q0 = w4[base], q1 = w4[base+1], q2 = w4[base+2], q3 = w4[base+3];
            acc[0]+=p*q0.x;  acc[1]+=p*q0.y;  acc[2]+=p*q0.z;  acc[3]+=p*q0.w;
            acc[4]+=p*q1.x;  acc[5]+=p*q1.y;  acc[6]+=p*q1.z;  acc[7]+=p*q1.w;
            acc[8]+=p*q2.x;  acc[9]+=p*q2.y;  acc[10]+=p*q2.z; acc[11]+=p*q2.w;
            acc[12]+=p*q3.x; acc[13]+=p*q3.y; acc[14]+=p*q3.z; acc[15]+=p*q3.w;
        }
    }

    const float sc = 0.125f;
    float4* op = (float4*)(x_out + (size_t)n * 16);
    op[0] = make_float4(acc[0]*sc,  acc[1]*sc,  acc[2]*sc,  acc[3]*sc);
    op[1] = make_float4(acc[4]*sc,  acc[5]*sc,  acc[6]*sc,  acc[7]*sc);
    op[2] = make_float4(acc[8]*sc,  acc[9]*sc,  acc[10]*sc, acc[11]*sc);
    op[3] = make_float4(acc[12]*sc, acc[13]*sc, acc[14]*sc, acc[15]*sc);
}

extern "C" void kernel_launch(void* const* d_in, const int* in_sizes, int n_in,
                              void* d_out, int out_size)
{
    const float* x    = (const float*)d_in[0];
    const int*   ei   = (const int*)  d_in[1];
    const float* attr = (const float*)d_in[2];
    const float* emb  = (const float*)d_in[3];
    const float* w1   = (const float*)d_in[4];
    const float* w2   = (const float*)d_in[5];
    const float* wn   = (const float*)d_in[6];

    float* out      = (float*)d_out;
    float* x_out    = out;                    // [N, 16]
    float* edge_out = out + N_NODES * 16;     // [E, 8]

    static int attr_set = 0;
    if (!attr_set) {
        cudaFuncSetAttribute(edge_kernel,
                             cudaFuncAttributeMaxDynamicSharedMemorySize,
                             SMEM_TOTAL);
        attr_set = 1;
    }

    zero_esum_kernel<<<(N_NODES * 8 + 511) / 512, 512>>>();
    edge_kernel<<<148, THREADS, SMEM_TOTAL>>>(x, ei, attr, emb, w1, w2, edge_out);
    node_kernel<<<(N_NODES + 255) / 256, 256>>>(x, wn, x_out);
}